// round 3
// baseline (speedup 1.0000x reference)
#include <cuda_runtime.h>
#include <cuda_bf16.h>

// AMMaskedLinear: B=64, IN=1024, OUT=1024, D=32.
//
// out[b,k] = om[b,k] * (cscale_b[k] * y[b,k] + cbias_b[k])
//   om[b,k] = (r_high[k] appears in hidden_rank[b,:])
//   y[b,k]  = sum_i [ r_low[i] present & 1 <= r_low[i] <= r_high[k] ]
//             * direction[k,i] * x[b,i]
//
// hidden_rank values are in [0,32] -> per-batch 33-bit presence bitmap.
// scale/bias reduce exactly to cscale_b / cbias_b (zeros @ W.T == 0).
// y is observable only when cscale_b[k] != 0 (dataset: always 0), so the
// matvec is gated (data-dependent, deterministic, graph-capture-safe).
//
// Layout: ONE WARP PER BATCH. 8 int4 loads/lane cover hidden_rank[b,:];
// r_high/cscale_b/cbias_b prefetched concurrently; bitmap via two
// __reduce_or_sync; 8 float4 stores/lane. No shared mem, no atomics,
// no __syncthreads -> single DRAM round trip on the critical path.

#define B_   64
#define IN_  1024
#define OUT_ 1024

__device__ __forceinline__ float slow_y(int k, unsigned long long p, int rh,
                                        const float* __restrict__ x,
                                        const int*   __restrict__ r_low,
                                        const float* __restrict__ direction,
                                        int b) {
    // Generic path: only reached when cscale_b[k] != 0 (never with dataset).
    const unsigned long long allowed = p & ((2ull << rh) - 2ull);
    const float* __restrict__ drow = direction + (size_t)k * IN_;
    const float* __restrict__ xrow = x + (size_t)b * IN_;
    float y = 0.0f;
    for (int i = 0; i < IN_; ++i)
        if ((allowed >> r_low[i]) & 1ull)
            y = fmaf(drow[i], xrow[i], y);
    return y;
}

__global__ __launch_bounds__(32, 1)
void am_masked_linear_kernel(const float* __restrict__ x,
                             const int*   __restrict__ hidden_rank,
                             const int*   __restrict__ r_low,
                             const int*   __restrict__ r_high,
                             const float* __restrict__ direction,
                             const float* __restrict__ cscale_b,
                             const float* __restrict__ cbias_b,
                             float*       __restrict__ out) {
    const int b    = blockIdx.x;
    const int lane = threadIdx.x;

    // ---- Issue ALL loads up front (independent; latency overlaps) ----
    const int4* __restrict__ hr4 =
        (const int4*)(hidden_rank + (size_t)b * IN_);
    int4 h[8];
    #pragma unroll
    for (int j = 0; j < 8; ++j) h[j] = hr4[j * 32 + lane];

    const int4*   __restrict__ rhp = (const int4*)r_high;
    const float4* __restrict__ scp = (const float4*)cscale_b;
    const float4* __restrict__ cbp = (const float4*)cbias_b;
    int4   rh4[8];
    float4 sc4[8];
    float4 cb4[8];
    #pragma unroll
    for (int j = 0; j < 8; ++j) {
        rh4[j] = rhp[j * 32 + lane];
        sc4[j] = scp[j * 32 + lane];
        cb4[j] = cbp[j * 32 + lane];
    }

    // ---- Presence bitmap of hidden_rank[b,:], values 0..32 ----
    unsigned int lo = 0u, hi = 0u;
    #pragma unroll
    for (int j = 0; j < 8; ++j) {
        const int v0 = h[j].x, v1 = h[j].y, v2 = h[j].z, v3 = h[j].w;
        lo |= (v0 < 32) ? (1u << v0) : 0u;  hi |= (v0 >= 32) ? 1u : 0u;
        lo |= (v1 < 32) ? (1u << v1) : 0u;  hi |= (v1 >= 32) ? 1u : 0u;
        lo |= (v2 < 32) ? (1u << v2) : 0u;  hi |= (v2 >= 32) ? 1u : 0u;
        lo |= (v3 < 32) ? (1u << v3) : 0u;  hi |= (v3 >= 32) ? 1u : 0u;
    }
    lo = __reduce_or_sync(0xffffffffu, lo);
    hi = __reduce_or_sync(0xffffffffu, hi);
    const unsigned long long p =
        ((unsigned long long)hi << 32) | (unsigned long long)lo;

    // ---- Emit 32 outputs per lane as 8 float4 stores ----
    float4* __restrict__ outp = (float4*)(out + (size_t)b * OUT_);
    #pragma unroll
    for (int j = 0; j < 8; ++j) {
        const int kbase = (j * 32 + lane) * 4;
        float4 r;
        {
            const int rh = rh4[j].x;
            const bool om = (p >> rh) & 1ull;
            float v = 0.0f;
            if (om) {
                const float sc = sc4[j].x;
                float y = 0.0f;
                if (sc != 0.0f && rh > 0)
                    y = slow_y(kbase + 0, p, rh, x, r_low, direction, b);
                v = fmaf(sc, y, cb4[j].x);
            }
            r.x = v;
        }
        {
            const int rh = rh4[j].y;
            const bool om = (p >> rh) & 1ull;
            float v = 0.0f;
            if (om) {
                const float sc = sc4[j].y;
                float y = 0.0f;
                if (sc != 0.0f && rh > 0)
                    y = slow_y(kbase + 1, p, rh, x, r_low, direction, b);
                v = fmaf(sc, y, cb4[j].y);
            }
            r.y = v;
        }
        {
            const int rh = rh4[j].z;
            const bool om = (p >> rh) & 1ull;
            float v = 0.0f;
            if (om) {
                const float sc = sc4[j].z;
                float y = 0.0f;
                if (sc != 0.0f && rh > 0)
                    y = slow_y(kbase + 2, p, rh, x, r_low, direction, b);
                v = fmaf(sc, y, cb4[j].z);
            }
            r.z = v;
        }
        {
            const int rh = rh4[j].w;
            const bool om = (p >> rh) & 1ull;
            float v = 0.0f;
            if (om) {
                const float sc = sc4[j].w;
                float y = 0.0f;
                if (sc != 0.0f && rh > 0)
                    y = slow_y(kbase + 3, p, rh, x, r_low, direction, b);
                v = fmaf(sc, y, cb4[j].w);
            }
            r.w = v;
        }
        outp[j * 32 + lane] = r;
    }
}

extern "C" void kernel_launch(void* const* d_in, const int* in_sizes, int n_in,
                              void* d_out, int out_size) {
    // metadata order: x, mask, pre_mask, hidden_rank, r_low, r_high,
    //                 direction, cscale_w, cscale_b, cbias_w, cbias_b
    const float* x           = (const float*)d_in[0];
    const int*   hidden_rank = (const int*)  d_in[3];
    const int*   r_low       = (const int*)  d_in[4];
    const int*   r_high      = (const int*)  d_in[5];
    const float* direction   = (const float*)d_in[6];
    const float* cscale_b    = (const float*)d_in[8];
    const float* cbias_b     = (const float*)d_in[10];
    float* out = (float*)d_out;

    am_masked_linear_kernel<<<B_, 32>>>(x, hidden_rank, r_low, r_high,
                                        direction, cscale_b, cbias_b, out);
}

// round 4
// speedup vs baseline: 1.3037x; 1.3037x over previous
#include <cuda_runtime.h>
#include <cuda_bf16.h>

// AMMaskedLinear: B=64, IN=1024, OUT=1024, D=32.
//
// out[b,k] = om[b,k] * (cscale_b[k] * y[b,k] + cbias_b[k])
//   om[b,k] = (r_high[k] appears in hidden_rank[b,:])
//   y[b,k]  = sum_i [ r_low[i] present & 1 <= r_low[i] <= r_high[k] ]
//             * direction[k,i] * x[b,i]
//
// hidden_rank values in [0,32] -> per-batch 33-bit presence bitmap replaces
// both O(1024^2) any(==) reductions. scale/bias reduce exactly to
// cscale_b / cbias_b (zeros @ W.T == 0). y observable only when
// cscale_b[k] != 0 (dataset: never), gated data-dependently (deterministic,
// graph-capture-safe); slow path is __noinline__ to keep hot path tiny.
//
// Layout: 256 threads per batch (8 warps). ALL loads prefetched before any
// barrier (one DRAM round trip total). Bitmap: warp __reduce_or_sync ->
// per-warp shared slot -> barrier -> 8 broadcast LDS + OR (no atomics).

#define B_   64
#define IN_  1024
#define OUT_ 1024

__device__ __noinline__ float slow_y(int k, unsigned long long p, int rh,
                                     const float* __restrict__ x,
                                     const int*   __restrict__ r_low,
                                     const float* __restrict__ direction,
                                     int b) {
    // Generic path: reached only when cscale_b[k] != 0 (never with dataset).
    const unsigned long long allowed = p & ((2ull << rh) - 2ull);
    const float* __restrict__ drow = direction + (size_t)k * IN_;
    const float* __restrict__ xrow = x + (size_t)b * IN_;
    float y = 0.0f;
    for (int i = 0; i < IN_; ++i)
        if ((allowed >> r_low[i]) & 1ull)
            y = fmaf(drow[i], xrow[i], y);
    return y;
}

__global__ __launch_bounds__(256, 1)
void am_masked_linear_kernel(const float* __restrict__ x,
                             const int*   __restrict__ hidden_rank,
                             const int*   __restrict__ r_low,
                             const int*   __restrict__ r_high,
                             const float* __restrict__ direction,
                             const float* __restrict__ cscale_b,
                             const float* __restrict__ cbias_b,
                             float*       __restrict__ out) {
    __shared__ uint2 s_bm[8];   // per-warp partial bitmaps {lo, hi}

    const int b    = blockIdx.x;
    const int tid  = threadIdx.x;
    const int wid  = tid >> 5;

    // ---- Prefetch EVERYTHING before any barrier (one DRAM round trip) ----
    const int4   h   = ((const int4*)  (hidden_rank + (size_t)b * IN_))[tid];
    const int4   rh4 = ((const int4*)  r_high  )[tid];
    const float4 sc4 = ((const float4*)cscale_b)[tid];
    const float4 cb4 = ((const float4*)cbias_b )[tid];

    // ---- Per-warp partial presence bitmap (values 0..32) ----
    unsigned int lo = 0u, hi = 0u;
    {
        const int v0 = h.x, v1 = h.y, v2 = h.z, v3 = h.w;
        lo |= (v0 < 32) ? (1u << v0) : 0u;  hi |= (v0 >= 32) ? 1u : 0u;
        lo |= (v1 < 32) ? (1u << v1) : 0u;  hi |= (v1 >= 32) ? 1u : 0u;
        lo |= (v2 < 32) ? (1u << v2) : 0u;  hi |= (v2 >= 32) ? 1u : 0u;
        lo |= (v3 < 32) ? (1u << v3) : 0u;  hi |= (v3 >= 32) ? 1u : 0u;
    }
    lo = __reduce_or_sync(0xffffffffu, lo);
    hi = __reduce_or_sync(0xffffffffu, hi);
    if ((tid & 31) == 0) s_bm[wid] = make_uint2(lo, hi);
    __syncthreads();

    // ---- Combine 8 warp partials (broadcast LDS, conflict-free) ----
    unsigned int flo = 0u, fhi = 0u;
    #pragma unroll
    for (int w = 0; w < 8; ++w) {
        const uint2 v = s_bm[w];
        flo |= v.x;  fhi |= v.y;
    }
    const unsigned long long p =
        ((unsigned long long)fhi << 32) | (unsigned long long)flo;

    // ---- 4 outputs per thread, one float4 store ----
    const int kbase = tid * 4;
    float4 r;
    {
        const int rh = rh4.x;
        float v = 0.0f;
        if ((p >> rh) & 1ull) {
            const float sc = sc4.x;
            float y = 0.0f;
            if (sc != 0.0f && rh > 0)
                y = slow_y(kbase + 0, p, rh, x, r_low, direction, b);
            v = fmaf(sc, y, cb4.x);
        }
        r.x = v;
    }
    {
        const int rh = rh4.y;
        float v = 0.0f;
        if ((p >> rh) & 1ull) {
            const float sc = sc4.y;
            float y = 0.0f;
            if (sc != 0.0f && rh > 0)
                y = slow_y(kbase + 1, p, rh, x, r_low, direction, b);
            v = fmaf(sc, y, cb4.y);
        }
        r.y = v;
    }
    {
        const int rh = rh4.z;
        float v = 0.0f;
        if ((p >> rh) & 1ull) {
            const float sc = sc4.z;
            float y = 0.0f;
            if (sc != 0.0f && rh > 0)
                y = slow_y(kbase + 2, p, rh, x, r_low, direction, b);
            v = fmaf(sc, y, cb4.z);
        }
        r.z = v;
    }
    {
        const int rh = rh4.w;
        float v = 0.0f;
        if ((p >> rh) & 1ull) {
            const float sc = sc4.w;
            float y = 0.0f;
            if (sc != 0.0f && rh > 0)
                y = slow_y(kbase + 3, p, rh, x, r_low, direction, b);
            v = fmaf(sc, y, cb4.w);
        }
        r.w = v;
    }
    ((float4*)(out + (size_t)b * OUT_))[tid] = r;
}

extern "C" void kernel_launch(void* const* d_in, const int* in_sizes, int n_in,
                              void* d_out, int out_size) {
    // metadata order: x, mask, pre_mask, hidden_rank, r_low, r_high,
    //                 direction, cscale_w, cscale_b, cbias_w, cbias_b
    const float* x           = (const float*)d_in[0];
    const int*   hidden_rank = (const int*)  d_in[3];
    const int*   r_low       = (const int*)  d_in[4];
    const int*   r_high      = (const int*)  d_in[5];
    const float* direction   = (const float*)d_in[6];
    const float* cscale_b    = (const float*)d_in[8];
    const float* cbias_b     = (const float*)d_in[10];
    float* out = (float*)d_out;

    am_masked_linear_kernel<<<B_, 256>>>(x, hidden_rank, r_low, r_high,
                                         direction, cscale_b, cbias_b, out);
}

// round 7
// speedup vs baseline: 1.6034x; 1.2299x over previous
#include <cuda_runtime.h>
#include <cuda_bf16.h>

// AMMaskedLinear: B=64, IN=1024, OUT=1024, D=32.
//
// out[b,k] = om[b,k] * (cscale_b[k] * y[b,k] + cbias_b[k])
//   om[b,k] = (r_high[k] appears in hidden_rank[b,:])
//   y[b,k]  = sum_i [ r_low[i] present & 1 <= r_low[i] <= r_high[k] ]
//             * direction[k,i] * x[b,i]
//
// hidden_rank values in [0,32] -> per-batch 33-bit presence bitmap replaces
// both O(1024^2) any(==) reductions. scale/bias reduce exactly to
// cscale_b / cbias_b (zeros @ W.T == 0). y is observable only when
// cscale_b[k] != 0 (dataset: never), gated data-dependently (deterministic,
// graph-capture-safe). All four per-thread slow-path checks are folded into
// ONE branch so the hot path is branch-free (pure SEL), removing the four
// BSSY/BSYNC envelopes seen in R4.
//
// Layout: 256 threads per batch (8 warps). ALL loads prefetched before the
// barrier (one DRAM/L2 round trip). Bitmap: warp __reduce_or_sync ->
// per-warp shared slot -> one barrier -> 8 broadcast LDS + OR.

#define B_   64
#define IN_  1024
#define OUT_ 1024

__device__ __noinline__ float slow_y(int k, unsigned long long p, int rh,
                                     const float* __restrict__ x,
                                     const int*   __restrict__ r_low,
                                     const float* __restrict__ direction,
                                     int b) {
    // Generic path: reached only when cscale_b[k] != 0 (never with dataset).
    const unsigned long long allowed = p & ((2ull << rh) - 2ull);
    const float* __restrict__ drow = direction + (size_t)k * IN_;
    const float* __restrict__ xrow = x + (size_t)b * IN_;
    float y = 0.0f;
    for (int i = 0; i < IN_; ++i)
        if ((allowed >> r_low[i]) & 1ull)
            y = fmaf(drow[i], xrow[i], y);
    return y;
}

__global__ __launch_bounds__(256, 1)
void am_masked_linear_kernel(const float* __restrict__ x,
                             const int*   __restrict__ hidden_rank,
                             const int*   __restrict__ r_low,
                             const int*   __restrict__ r_high,
                             const float* __restrict__ direction,
                             const float* __restrict__ cscale_b,
                             const float* __restrict__ cbias_b,
                             float*       __restrict__ out) {
    __shared__ uint2 s_bm[8];   // per-warp partial bitmaps {lo, hi}

    const int b   = blockIdx.x;
    const int tid = threadIdx.x;
    const int wid = tid >> 5;

    // ---- Critical-chain load first, then the rest (all pre-barrier) ----
    const int4   h   = ((const int4*)  (hidden_rank + (size_t)b * IN_))[tid];
    const int4   rh4 = ((const int4*)  r_high  )[tid];
    const float4 cb4 = ((const float4*)cbias_b )[tid];
    const float4 sc4 = ((const float4*)cscale_b)[tid];

    // ---- Per-warp partial presence bitmap (values 0..32) ----
    unsigned int lo = 0u, hi = 0u;
    {
        const int v0 = h.x, v1 = h.y, v2 = h.z, v3 = h.w;
        lo |= (v0 < 32) ? (1u << v0) : 0u;  hi |= (v0 >= 32) ? 1u : 0u;
        lo |= (v1 < 32) ? (1u << v1) : 0u;  hi |= (v1 >= 32) ? 1u : 0u;
        lo |= (v2 < 32) ? (1u << v2) : 0u;  hi |= (v2 >= 32) ? 1u : 0u;
        lo |= (v3 < 32) ? (1u << v3) : 0u;  hi |= (v3 >= 32) ? 1u : 0u;
    }
    lo = __reduce_or_sync(0xffffffffu, lo);
    hi = __reduce_or_sync(0xffffffffu, hi);
    if ((tid & 31) == 0) s_bm[wid] = make_uint2(lo, hi);
    __syncthreads();

    // ---- Combine 8 warp partials (broadcast LDS, conflict-free) ----
    unsigned int flo = 0u, fhi = 0u;
    #pragma unroll
    for (int w = 0; w < 8; ++w) {
        const uint2 v = s_bm[w];
        flo |= v.x;  fhi |= v.y;
    }
    const unsigned long long p =
        ((unsigned long long)fhi << 32) | (unsigned long long)flo;

    // ---- Branch-free fast path: v = om ? cbias : 0 (SEL, no BSSY) ----
    const int rh0 = rh4.x, rh1 = rh4.y, rh2 = rh4.z, rh3 = rh4.w;
    const bool om0 = (p >> rh0) & 1ull;
    const bool om1 = (p >> rh1) & 1ull;
    const bool om2 = (p >> rh2) & 1ull;
    const bool om3 = (p >> rh3) & 1ull;

    float4 r;
    r.x = om0 ? cb4.x : 0.0f;
    r.y = om1 ? cb4.y : 0.0f;
    r.z = om2 ? cb4.z : 0.0f;
    r.w = om3 ? cb4.w : 0.0f;

    // ---- ONE combined slow-path branch (never taken with dataset) ----
    const bool s0 = om0 & (sc4.x != 0.0f) & (rh0 > 0);
    const bool s1 = om1 & (sc4.y != 0.0f) & (rh1 > 0);
    const bool s2 = om2 & (sc4.z != 0.0f) & (rh2 > 0);
    const bool s3 = om3 & (sc4.w != 0.0f) & (rh3 > 0);
    if (s0 | s1 | s2 | s3) {
        const int kbase = tid * 4;
        if (s0) r.x = fmaf(sc4.x, slow_y(kbase + 0, p, rh0, x, r_low, direction, b), cb4.x);
        if (s1) r.y = fmaf(sc4.y, slow_y(kbase + 1, p, rh1, x, r_low, direction, b), cb4.y);
        if (s2) r.z = fmaf(sc4.z, slow_y(kbase + 2, p, rh2, x, r_low, direction, b), cb4.z);
        if (s3) r.w = fmaf(sc4.w, slow_y(kbase + 3, p, rh3, x, r_low, direction, b), cb4.w);
    }

    ((float4*)(out + (size_t)b * OUT_))[tid] = r;
}

extern "C" void kernel_launch(void* const* d_in, const int* in_sizes, int n_in,
                              void* d_out, int out_size) {
    // metadata order: x, mask, pre_mask, hidden_rank, r_low, r_high,
    //                 direction, cscale_w, cscale_b, cbias_w, cbias_b
    const float* x           = (const float*)d_in[0];
    const int*   hidden_rank = (const int*)  d_in[3];
    const int*   r_low       = (const int*)  d_in[4];
    const int*   r_high      = (const int*)  d_in[5];
    const float* direction   = (const float*)d_in[6];
    const float* cscale_b    = (const float*)d_in[8];
    const float* cbias_b     = (const float*)d_in[10];
    float* out = (float*)d_out;

    am_masked_linear_kernel<<<B_, 256>>>(x, hidden_rank, r_low, r_high,
                                         direction, cscale_b, cbias_b, out);
}